// round 9
// baseline (speedup 1.0000x reference)
#include <cuda_runtime.h>
#include <cstdint>
#include <math_constants.h>

// Problem constants
#define BATCH 64
#define M     4096   // NPROP (columns)
#define NGTC  128    // max GT (rows)
#define NT    512    // threads per CTA
#define CPT   (M/NT) // 8 columns per thread
#define NW    (NT/32)
#define KINF  0xFFFFFFFFFFFFFFFFull
#define EPSF  1e-4f  // proxy slack: >> max fp32-proxy error (~6e-6), << typical cost gaps

// Order-preserving double <-> uint64
__device__ __forceinline__ unsigned long long ord64(double x) {
    long long s = __double_as_longlong(x);
    return (unsigned long long)s ^ ((unsigned long long)(s >> 63) | 0x8000000000000000ull);
}
__device__ __forceinline__ double unord64(unsigned long long kk) {
    long long b = (kk & 0x8000000000000000ull) ? (long long)(kk ^ 0x8000000000000000ull)
                                               : (long long)(~kk);
    return __longlong_as_double(b);
}
__device__ __forceinline__ unsigned long long ullmin2(unsigned long long a, unsigned long long b) {
    return a < b ? a : b;
}

__global__ __launch_bounds__(NT, 1)
void matcher_kernel(const int*   __restrict__ nag,   // [B]
                    const float* __restrict__ gtn,   // [B][NGT][3]
                    const float* __restrict__ qn,    // [M][3]
                    float*       __restrict__ out)   // [2][B][M] : inds then mask
{
    const int b    = blockIdx.x;
    const int tid  = threadIdx.x;
    const int lane = tid & 31;
    const int wid  = tid >> 5;

    __shared__ short              p[M + 1];        // column -> matched row (1-based), 0 = free
    __shared__ unsigned short     way[M + 1];      // predecessor column (0 = from cur row)
    __shared__ double             u[NGTC + 1];     // row duals
    __shared__ float              gns[NGTC * 3];   // gt normals for this batch
    __shared__ __align__(64) float wredf[2][NW];   // per-warp proxy min (parity-buffered)
    __shared__ unsigned long long slotKey[2];      // exact winner key (parity-buffered)
    __shared__ unsigned int       slotJ[2];        // exact winner column

    const int k = nag[b];

    for (int j = tid; j <= M; j += NT) p[j] = 0;
    for (int j = tid; j <= NGTC; j += NT) u[j] = 0.0;
    for (int j = tid; j < k * 3; j += NT) gns[j] = gtn[(size_t)b * NGTC * 3 + j];

    // per-thread column state (8 cols, strided by NT)
    float  q0[CPT], q1[CPT], q2[CPT];  // query normals
    float  dot[CPT];                   // this step's fp32 dot (bit-identical to ref C path)
    float  vf[CPT], df32[CPT];         // fp32 proxies of v and d
    double v[CPT];                     // exact column duals
    unsigned long long dk[CPT];        // exact d as ordered uint64 key
    #pragma unroll
    for (int t = 0; t < CPT; t++) {
        int c = tid + t * NT;
        q0[t] = qn[c * 3 + 0];
        q1[t] = qn[c * 3 + 1];
        q2[t] = qn[c * 3 + 2];
        v[t]  = 0.0;
    }
    __syncthreads();

    int par = 0;

    for (int i = 1; i <= k; i++) {
        unsigned usedmask = 0;
        #pragma unroll
        for (int t = 0; t < CPT; t++) {
            dk[t]   = KINF;
            df32[t] = CUDART_INF_F;
            vf[t]   = (float)v[t];     // exact rounding of current dual
        }

        int    i0 = i, j0 = 0, jend = 0;
        double minVal = 0.0;

        while (true) {
            const double h1  = minVal - u[i0] + 1.0;   // folds the "1 - dot" constant
            const float  h1f = (float)h1;
            const float  gx  = gns[(i0 - 1) * 3 + 0];
            const float  gy  = gns[(i0 - 1) * 3 + 1];
            const float  gz  = gns[(i0 - 1) * 3 + 2];

            // ---- pass 1: fp32 proxy min over min(d, r), no index tracking ----
            float pmin = CUDART_INF_F;
            #pragma unroll
            for (int t = 0; t < CPT; t++) {
                dot[t] = fmaf(q2[t], gz, fmaf(q1[t], gy, q0[t] * gx));
                float rf = (h1f - vf[t]) - dot[t];     // vf poisoned (-3e38) on used cols -> huge
                pmin = fminf(pmin, fminf(df32[t], rf));
            }
            #pragma unroll
            for (int off = 16; off; off >>= 1)
                pmin = fminf(pmin, __shfl_down_sync(0xFFFFFFFFu, pmin, off));
            if (lane == 0) wredf[par][wid] = pmin;
            if (tid == 0) { slotKey[par] = KINF; slotJ[par] = 0xFFFFFFFFu; }
            __syncthreads();                           // bar 1

            float pm2 = CUDART_INF_F;
            #pragma unroll
            for (int w = 0; w < NW; w++) pm2 = fminf(pm2, wredf[par][w]);
            const float thr = pm2 + EPSF;

            // ---- stage 1: exact keys for candidates only (usually 1 thread) ----
            unsigned long long myCk = KINF;
            unsigned int       myJ  = 0xFFFFFFFFu;
            #pragma unroll
            for (int t = 0; t < CPT; t++) {
                float rf = (h1f - vf[t]) - dot[t];
                if (fminf(df32[t], rf) <= thr) {
                    double re = (h1 - v[t]) - (double)dot[t];
                    unsigned long long ck = ullmin2(ord64(re), dk[t]);
                    if (ck < myCk) { myCk = ck; myJ = (unsigned)(tid + t * NT + 1); }
                }
            }
            if (myCk != KINF) atomicMin(&slotKey[par], myCk);
            __syncthreads();                           // bar 2

            const unsigned long long winKey = slotKey[par];
            if (myCk == winKey) atomicMin(&slotJ[par], myJ);
            __syncthreads();                           // bar 3

            const int j1 = (int)slotJ[par];
            minVal = unord64(winKey);
            par ^= 1;

            const int pmatch = p[j1];
            if (pmatch == 0) {
                // fast path: phase ends, no d-merge. Patch only winner's 'way'.
                int c = j1 - 1;
                if ((c & (NT - 1)) == tid) {
                    int t = c >> 9;
                    double re = (h1 - v[t]) - (double)dot[t];
                    if (ord64(re) < dk[t]) way[j1] = (unsigned short)j0;
                }
                jend = j1;
                break;
            }

            // ---- slow path: exact merge of this row's relax into d ----
            #pragma unroll
            for (int t = 0; t < CPT; t++) {
                if (!((usedmask >> t) & 1u)) {
                    int j = tid + t * NT + 1;
                    double re = (h1 - v[t]) - (double)dot[t];
                    unsigned long long rk = ord64(re);
                    if (rk < dk[t]) {
                        dk[t]   = rk;
                        df32[t] = (float)re;
                        way[j]  = (unsigned short)j0;
                    }
                }
            }
            // mark j1 scanned (poison proxies; dk[j1] frozen at minVal)
            {
                int c = j1 - 1;
                if ((c & (NT - 1)) == tid) {
                    int t = c >> 9;
                    usedmask |= 1u << t;
                    vf[t]   = -3e38f;
                    df32[t] = CUDART_INF_F;
                }
            }
            i0 = pmatch;
            j0 = j1;
        }

        // ---- phase-end dual updates (scanned set only) ----
        #pragma unroll
        for (int t = 0; t < CPT; t++) {
            if ((usedmask >> t) & 1u) {
                double adj = minVal - unord64(dk[t]);
                v[t] -= adj;
                int j = tid + t * NT + 1;
                u[p[j]] += adj;        // distinct rows across scanned cols
            }
        }
        if (tid == 0) u[i] += minVal;
        __syncthreads();

        if (tid == 0) {                // augment along predecessor chain
            int j = jend;
            while (true) {
                int jp = way[j];
                if (jp == 0) { p[j] = (short)i; break; }
                p[j] = p[jp];
                j = jp;
            }
        }
        __syncthreads();
    }

    // ---- outputs: [0] per_prop_gt_inds, [1] proposal_matched_mask ----
    float* outInds = out + (size_t)b * M;
    float* outMask = out + (size_t)BATCH * M + (size_t)b * M;
    #pragma unroll
    for (int t = 0; t < CPT; t++) {
        int c = tid + t * NT;
        int r = p[c + 1];
        outInds[c] = (r > 0) ? (float)(r - 1) : 0.0f;
        outMask[c] = (r > 0) ? 1.0f : 0.0f;
    }
}

extern "C" void kernel_launch(void* const* d_in, const int* in_sizes, int n_in,
                              void* d_out, int out_size) {
    // metadata order: cls_prob[0], gt_box_present[1], num_actual_gt[2],
    //                 gt_normal_normalized[3], query_normals[4]
    const int*   nag = (const int*)  d_in[2];
    const float* gtn = (const float*)d_in[3];
    const float* qn  = (const float*)d_in[4];
    matcher_kernel<<<BATCH, NT>>>(nag, gtn, qn, (float*)d_out);
}

// round 10
// speedup vs baseline: 1.3727x; 1.3727x over previous
#include <cuda_runtime.h>
#include <cstdint>

// Problem constants
#define BATCH 64
#define M     4096   // NPROP (columns)
#define NGTC  128    // max GT (rows)
#define NT    256    // threads per CTA
#define CPT   (M/NT) // 16 columns per thread
#define NW    (NT/32)// 8 warps
#define LOGNT 8      // log2(NT)

// Order-preserving double <-> uint64 (total order identical to operator< on doubles)
__device__ __forceinline__ unsigned long long ord64(double x) {
    long long s = __double_as_longlong(x);
    return (unsigned long long)s ^ ((unsigned long long)(s >> 63) | 0x8000000000000000ull);
}
__device__ __forceinline__ double unord64(unsigned long long k) {
    long long b = (k & 0x8000000000000000ull) ? (long long)(k ^ 0x8000000000000000ull)
                                              : (long long)(~k);
    return __longlong_as_double(b);
}

__global__ __launch_bounds__(NT, 1)
void matcher_kernel(const int*   __restrict__ nag,   // [B]
                    const float* __restrict__ gtn,   // [B][NGT][3]
                    const float* __restrict__ qn,    // [M][3]
                    float*       __restrict__ out)   // [2][B][M] : inds then mask
{
    const int b    = blockIdx.x;
    const int tid  = threadIdx.x;
    const int lane = tid & 31;
    const int wid  = tid >> 5;

    __shared__ short              p[M + 1];      // column -> matched row (1-based), 0 = free
    __shared__ unsigned short     way[M + 1];    // predecessor column (0 = from cur row)
    __shared__ double             u[NGTC + 1];   // row duals (1-based)
    __shared__ float              gns[NGTC * 3]; // gt normals for this batch
    __shared__ unsigned long long wkey[2][NW];   // per-warp min key (parity-buffered)
    __shared__ int                wjj[2][NW];    // per-warp argmin column

    const int k = nag[b];

    // ---- init shared state ----
    for (int j = tid; j <= M; j += NT) p[j] = 0;
    for (int j = tid; j <= NGTC; j += NT) u[j] = 0.0;
    for (int j = tid; j < k * 3; j += NT) gns[j] = gtn[(size_t)b * NGTC * 3 + j];

    // ---- per-thread register state (16 columns, strided by NT) ----
    float  q0[CPT], q1[CPT], q2[CPT];
    double v[CPT], d[CPT];   // column duals + absolute shortest-path costs
    #pragma unroll
    for (int t = 0; t < CPT; t++) {
        int c = tid + t * NT;
        q0[t] = qn[c * 3 + 0];
        q1[t] = qn[c * 3 + 1];
        q2[t] = qn[c * 3 + 2];
        v[t]  = 0.0;
    }
    __syncthreads();

    const double DINF = 1e300;
    int par = 0;   // parity for double-buffered reduction scratch

    // ---- LAPJV shortest augmenting path, one row per phase ----
    for (int i = 1; i <= k; i++) {
        unsigned usedmask = 0;
        #pragma unroll
        for (int t = 0; t < CPT; t++) d[t] = DINF;

        int    i0 = i, j0 = 0, jend = 0;
        double minVal = 0.0;

        while (true) {
            // uniform per-step scalars (u constant during a phase)
            const double h1 = minVal - u[i0] + 1.0;   // folds the "1 - dot" constant
            const float  gx = gns[(i0 - 1) * 3 + 0];
            const float  gy = gns[(i0 - 1) * 3 + 1];
            const float  gz = gns[(i0 - 1) * 3 + 2];

            // ---- relax free columns (exact f64), track local argmin ----
            double best  = DINF;
            int    bestj = M + 1;
            #pragma unroll
            for (int t = 0; t < CPT; t++) {
                if (!((usedmask >> t) & 1u)) {
                    int   j   = tid + t * NT + 1;
                    float dot = fmaf(q2[t], gz, fmaf(q1[t], gy, q0[t] * gx));
                    double r  = (h1 - v[t]) - (double)dot;  // minVal + (1-dot) - u[i0] - v[j]
                    if (r < d[t]) { d[t] = r; way[j] = (unsigned short)j0; }
                    // per-thread js ascend with t -> strict < keeps smallest j on ties
                    if (d[t] < best) { best = d[t]; bestj = j; }
                }
            }

            // ---- stage 1: warp butterfly argmin on (ord64 key, j) ----
            unsigned long long bk = ord64(best);
            #pragma unroll
            for (int off = 16; off; off >>= 1) {
                unsigned long long ok = __shfl_xor_sync(0xFFFFFFFFu, bk,    off);
                int                oj = __shfl_xor_sync(0xFFFFFFFFu, bestj, off);
                if (ok < bk || (ok == bk && oj < bestj)) { bk = ok; bestj = oj; }
            }
            if (lane == 0) { wkey[par][wid] = bk; wjj[par][wid] = bestj; }
            __syncthreads();   // the ONLY barrier in the step

            // ---- stage 2: every warp reduces the 8 partials redundantly ----
            unsigned long long gk = wkey[par][lane & 7];
            int                gj = wjj[par][lane & 7];
            #pragma unroll
            for (int off = 4; off; off >>= 1) {
                unsigned long long ok = __shfl_xor_sync(0xFFFFFFFFu, gk, off);
                int                oj = __shfl_xor_sync(0xFFFFFFFFu, gj, off);
                if (ok < gk || (ok == gk && oj < gj)) { gk = ok; gj = oj; }
            }
            minVal = unord64(gk);
            const int j1 = gj;
            par ^= 1;

            const int pmatch = p[j1];        // p stable during the phase
            if (pmatch == 0) { jend = j1; break; }

            // mark j1 scanned (register bitmask on owning thread)
            { int c = j1 - 1; if ((c & (NT - 1)) == tid) usedmask |= 1u << (c >> LOGNT); }
            i0 = pmatch;
            j0 = j1;
        }

        // ---- phase-end dual updates (scanned set only), BEFORE augmentation ----
        #pragma unroll
        for (int t = 0; t < CPT; t++) {
            if ((usedmask >> t) & 1u) {
                double adj = minVal - d[t];
                v[t] -= adj;                         // v[j] -= minVal - d[j]
                int j = tid + t * NT + 1;
                u[p[j]] += adj;                      // distinct rows across scanned cols
            }
        }
        if (tid == 0) u[i] += minVal;
        __syncthreads();                             // u writes + p/way reads done

        if (tid == 0) {                              // augment along predecessor chain
            int j = jend;
            while (true) {
                int jp = way[j];
                if (jp == 0) { p[j] = (short)i; break; }
                p[j] = p[jp];
                j = jp;
            }
        }
        __syncthreads();                             // p/way stable before next phase
    }

    // ---- write outputs: [0] per_prop_gt_inds, [1] proposal_matched_mask ----
    float* outInds = out + (size_t)b * M;
    float* outMask = out + (size_t)BATCH * M + (size_t)b * M;
    #pragma unroll
    for (int t = 0; t < CPT; t++) {
        int c = tid + t * NT;
        int r = p[c + 1];
        outInds[c] = (r > 0) ? (float)(r - 1) : 0.0f;
        outMask[c] = (r > 0) ? 1.0f : 0.0f;
    }
}

extern "C" void kernel_launch(void* const* d_in, const int* in_sizes, int n_in,
                              void* d_out, int out_size) {
    // metadata order: cls_prob[0], gt_box_present[1], num_actual_gt[2],
    //                 gt_normal_normalized[3], query_normals[4]
    const int*   nag = (const int*)  d_in[2];
    const float* gtn = (const float*)d_in[3];
    const float* qn  = (const float*)d_in[4];
    matcher_kernel<<<BATCH, NT>>>(nag, gtn, qn, (float*)d_out);
}

// round 11
// speedup vs baseline: 1.6193x; 1.1796x over previous
#include <cuda_runtime.h>
#include <cstdint>

// Problem constants
#define BATCH 64
#define M     4096   // NPROP (columns)
#define NGTC  128    // max GT (rows)
#define NT    512    // threads per CTA
#define CPT   (M/NT) // 8 columns per thread
#define NW    (NT/32)// 16 warps
#define LOGNT 9      // log2(NT)
#define KINF  0xFFFFFFFFFFFFFFFFull

// Order-preserving double <-> uint64 (total order identical to operator< on doubles)
__device__ __forceinline__ unsigned long long ord64(double x) {
    long long s = __double_as_longlong(x);
    return (unsigned long long)s ^ ((unsigned long long)(s >> 63) | 0x8000000000000000ull);
}
__device__ __forceinline__ double unord64(unsigned long long k) {
    long long b = (k & 0x8000000000000000ull) ? (long long)(k ^ 0x8000000000000000ull)
                                              : (long long)(~k);
    return __longlong_as_double(b);
}

__global__ __launch_bounds__(NT, 1)
void matcher_kernel(const int*   __restrict__ nag,   // [B]
                    const float* __restrict__ gtn,   // [B][NGT][3]
                    const float* __restrict__ qn,    // [M][3]
                    float*       __restrict__ out)   // [2][B][M] : inds then mask
{
    const int b    = blockIdx.x;
    const int tid  = threadIdx.x;
    const int lane = tid & 31;
    const int wid  = tid >> 5;

    __shared__ short              p[M + 1];      // column -> matched row (1-based), 0 = free
    __shared__ unsigned short     way[M + 1];    // predecessor column (0 = from cur row)
    __shared__ double             u[NGTC + 1];   // row duals (1-based)
    __shared__ float              gns[NGTC * 3]; // gt normals for this batch
    __shared__ unsigned long long wkey[2][NW];   // per-warp min key (parity-buffered)
    __shared__ int                wjj[2][NW];    // per-warp argmin column

    const int k = nag[b];

    // ---- init shared state ----
    for (int j = tid; j <= M; j += NT) p[j] = 0;
    for (int j = tid; j <= NGTC; j += NT) u[j] = 0.0;
    for (int j = tid; j < k * 3; j += NT) gns[j] = gtn[(size_t)b * NGTC * 3 + j];

    // ---- per-thread register state (8 columns, strided by NT) ----
    float  q0[CPT], q1[CPT], q2[CPT];
    double v[CPT], d[CPT];   // column duals + absolute shortest-path costs
    #pragma unroll
    for (int t = 0; t < CPT; t++) {
        int c = tid + t * NT;
        q0[t] = qn[c * 3 + 0];
        q1[t] = qn[c * 3 + 1];
        q2[t] = qn[c * 3 + 2];
        v[t]  = 0.0;
    }
    __syncthreads();

    const double DINF = 1e300;
    int par = 0;   // parity for double-buffered reduction scratch

    // ---- LAPJV shortest augmenting path, one row per phase ----
    for (int i = 1; i <= k; i++) {
        unsigned usedmask = 0;
        #pragma unroll
        for (int t = 0; t < CPT; t++) d[t] = DINF;

        int    i0 = i, j0 = 0, jend = 0;
        double minVal = 0.0;

        while (true) {
            // uniform per-step scalars (u constant during a phase)
            const double h1 = minVal - u[i0] + 1.0;   // folds the "1 - dot" constant
            const float  gx = gns[(i0 - 1) * 3 + 0];
            const float  gy = gns[(i0 - 1) * 3 + 1];
            const float  gz = gns[(i0 - 1) * 3 + 2];

            // ---- relax: all 8 columns independent (ILP), no serial best-chain ----
            #pragma unroll
            for (int t = 0; t < CPT; t++) {
                float dot = fmaf(q2[t], gz, fmaf(q1[t], gy, q0[t] * gx));
                double r  = (h1 - v[t]) - (double)dot;  // minVal + (1-dot) - u[i0] - v[j]
                if (!((usedmask >> t) & 1u) && r < d[t]) {
                    d[t] = r;
                    way[tid + t * NT + 1] = (unsigned short)j0;
                }
            }

            // masked ord64 keys (independent per t, ALU pipe)
            unsigned long long kk[CPT];
            #pragma unroll
            for (int t = 0; t < CPT; t++)
                kk[t] = ((usedmask >> t) & 1u) ? KINF : ord64(d[t]);

            // ---- 3-level pairwise tournament (int compares; smaller t wins ties) ----
            unsigned long long ka, kb; int ta, tb;
            ka = kk[0]; ta = 0; if (kk[1] < ka) { ka = kk[1]; ta = 1; }
            kb = kk[2]; tb = 2; if (kk[3] < kb) { kb = kk[3]; tb = 3; }
            if (kb < ka) { ka = kb; ta = tb; }
            kb = kk[4]; tb = 4; if (kk[5] < kb) { kb = kk[5]; tb = 5; }
            { unsigned long long kc = kk[6]; int tc = 6;
              if (kk[7] < kc) { kc = kk[7]; tc = 7; }
              if (kc < kb) { kb = kc; tb = tc; } }
            if (kb < ka) { ka = kb; ta = tb; }
            unsigned long long bk = ka;
            int bestj = tid + ta * NT + 1;

            // ---- stage 1: warp butterfly argmin on (key, j), int compares ----
            #pragma unroll
            for (int off = 16; off; off >>= 1) {
                unsigned long long ok = __shfl_xor_sync(0xFFFFFFFFu, bk,    off);
                int                oj = __shfl_xor_sync(0xFFFFFFFFu, bestj, off);
                if (ok < bk || (ok == bk && oj < bestj)) { bk = ok; bestj = oj; }
            }
            if (lane == 0) { wkey[par][wid] = bk; wjj[par][wid] = bestj; }
            __syncthreads();   // the ONLY barrier in the step

            // ---- stage 2: every warp reduces the 16 partials redundantly ----
            unsigned long long gk = wkey[par][lane & 15];
            int                gj = wjj[par][lane & 15];
            #pragma unroll
            for (int off = 8; off; off >>= 1) {
                unsigned long long ok = __shfl_xor_sync(0xFFFFFFFFu, gk, off);
                int                oj = __shfl_xor_sync(0xFFFFFFFFu, gj, off);
                if (ok < gk || (ok == gk && oj < gj)) { gk = ok; gj = oj; }
            }
            minVal = unord64(gk);
            const int j1 = gj;
            par ^= 1;

            const int pmatch = p[j1];        // p stable during the phase
            if (pmatch == 0) { jend = j1; break; }

            // mark j1 scanned (register bitmask on owning thread)
            { int c = j1 - 1; if ((c & (NT - 1)) == tid) usedmask |= 1u << (c >> LOGNT); }
            i0 = pmatch;
            j0 = j1;
        }

        // ---- phase-end dual updates (scanned set only), BEFORE augmentation ----
        #pragma unroll
        for (int t = 0; t < CPT; t++) {
            if ((usedmask >> t) & 1u) {
                double adj = minVal - d[t];
                v[t] -= adj;                         // v[j] -= minVal - d[j]
                int j = tid + t * NT + 1;
                u[p[j]] += adj;                      // distinct rows across scanned cols
            }
        }
        if (tid == 0) u[i] += minVal;
        __syncthreads();                             // u writes + p/way reads done

        if (tid == 0) {                              // augment along predecessor chain
            int j = jend;
            while (true) {
                int jp = way[j];
                if (jp == 0) { p[j] = (short)i; break; }
                p[j] = p[jp];
                j = jp;
            }
        }
        __syncthreads();                             // p/way stable before next phase
    }

    // ---- write outputs: [0] per_prop_gt_inds, [1] proposal_matched_mask ----
    float* outInds = out + (size_t)b * M;
    float* outMask = out + (size_t)BATCH * M + (size_t)b * M;
    #pragma unroll
    for (int t = 0; t < CPT; t++) {
        int c = tid + t * NT;
        int r = p[c + 1];
        outInds[c] = (r > 0) ? (float)(r - 1) : 0.0f;
        outMask[c] = (r > 0) ? 1.0f : 0.0f;
    }
}

extern "C" void kernel_launch(void* const* d_in, const int* in_sizes, int n_in,
                              void* d_out, int out_size) {
    // metadata order: cls_prob[0], gt_box_present[1], num_actual_gt[2],
    //                 gt_normal_normalized[3], query_normals[4]
    const int*   nag = (const int*)  d_in[2];
    const float* gtn = (const float*)d_in[3];
    const float* qn  = (const float*)d_in[4];
    matcher_kernel<<<BATCH, NT>>>(nag, gtn, qn, (float*)d_out);
}

// round 12
// speedup vs baseline: 5.5090x; 3.4021x over previous
#include <cuda_runtime.h>
#include <cstdint>
#include <math_constants.h>

// Problem constants
#define BATCH 64
#define M     4096   // NPROP (columns)
#define NGTC  128    // max GT (rows)
#define NT    512    // threads per CTA
#define CPT   (M/NT) // 8 columns per thread
#define NW    (NT/32)// 16 warps
#define LOGNT 9      // log2(NT)
#define RT    8      // rows per init tile
#define KINF  0xFFFFFFFFFFFFFFFFull

// Order-preserving float <-> uint32
__device__ __forceinline__ unsigned f2o(float f) {
    unsigned x = __float_as_uint(f);
    return x ^ ((x & 0x80000000u) ? 0xFFFFFFFFu : 0x80000000u);
}
__device__ __forceinline__ float o2f(unsigned x) {
    unsigned w = (x & 0x80000000u) ? (x ^ 0x80000000u) : ~x;
    return __uint_as_float(w);
}
// Order-preserving double <-> uint64
__device__ __forceinline__ unsigned long long ord64(double x) {
    long long s = __double_as_longlong(x);
    return (unsigned long long)s ^ ((unsigned long long)(s >> 63) | 0x8000000000000000ull);
}
__device__ __forceinline__ double unord64(unsigned long long k) {
    long long b = (k & 0x8000000000000000ull) ? (long long)(k ^ 0x8000000000000000ull)
                                              : (long long)(~k);
    return __longlong_as_double(b);
}

__global__ __launch_bounds__(NT, 1)
void matcher_kernel(const int*   __restrict__ nag,   // [B]
                    const float* __restrict__ gtn,   // [B][NGT][3]
                    const float* __restrict__ qn,    // [M][3]
                    float*       __restrict__ out)   // [2][B][M] : inds then mask
{
    const int b    = blockIdx.x;
    const int tid  = threadIdx.x;
    const int lane = tid & 31;
    const int wid  = tid >> 5;

    __shared__ short              p[M + 1];        // column -> matched row (1-based), 0 = free
    __shared__ unsigned short     way[M + 1];      // predecessor column (0 = from cur row)
    __shared__ double             u[NGTC + 1];     // row duals (1-based)
    __shared__ float              gns[NGTC * 3];   // gt normals for this batch
    __shared__ unsigned long long wkey[2][NW];     // phase reduction (parity-buffered)
    __shared__ int                wjj[2][NW];
    __shared__ unsigned long long awk[RT][NW];     // init: per-warp (cost,j) keys per row
    __shared__ unsigned long long rowbest[RT];     // init: per-row winner
    __shared__ short              plist[NGTC];     // rows needing a full phase
    __shared__ int                npend;

    const int k = nag[b];

    // ---- init shared state ----
    for (int j = tid; j <= M; j += NT) p[j] = 0;
    for (int j = tid; j < k * 3; j += NT) gns[j] = gtn[(size_t)b * NGTC * 3 + j];
    if (tid == 0) npend = 0;

    // ---- per-thread query normals (8 columns, strided by NT) ----
    float q0[CPT], q1[CPT], q2[CPT];
    #pragma unroll
    for (int t = 0; t < CPT; t++) {
        int c = tid + t * NT;
        q0[t] = qn[c * 3 + 0];
        q1[t] = qn[c * 3 + 1];
        q2[t] = qn[c * 3 + 2];
    }
    __syncthreads();

    // ================= Phase A: greedy row-reduction init =================
    // u[i] = min_j C[i,j] (fp32, identical rounding to reference C);
    // row claims its argmin column if free, else joins pending list.
    for (int base = 1; base <= k; base += RT) {
        const int nr = min(RT, k - base + 1);
        float bc[RT]; int bj[RT];
        for (int r = 0; r < nr; r++) {
            const float gx = gns[(base - 1 + r) * 3 + 0];
            const float gy = gns[(base - 1 + r) * 3 + 1];
            const float gz = gns[(base - 1 + r) * 3 + 2];
            float bcr = CUDART_INF_F; int bjr = M;
            #pragma unroll
            for (int t = 0; t < CPT; t++) {
                float dot = fmaf(q2[t], gz, fmaf(q1[t], gy, q0[t] * gx));
                float cf  = 1.0f - dot;                 // matches reference C bit-for-bit
                if (cf < bcr) { bcr = cf; bjr = tid + t * NT + 1; }  // first-min => smallest j
            }
            bc[r] = bcr; bj[r] = bjr;
        }
        for (int r = 0; r < nr; r++) {
            unsigned long long kk = ((unsigned long long)f2o(bc[r]) << 32) | (unsigned)bj[r];
            #pragma unroll
            for (int off = 16; off; off >>= 1) {
                unsigned long long ok = __shfl_xor_sync(0xFFFFFFFFu, kk, off);
                if (ok < kk) kk = ok;                   // min cost, then min j
            }
            if (lane == 0) awk[r][wid] = kk;
        }
        __syncthreads();
        if (wid < nr) {                                  // warp w finishes row w
            unsigned long long kk = awk[wid][lane & 15];
            #pragma unroll
            for (int off = 8; off; off >>= 1) {
                unsigned long long ok = __shfl_xor_sync(0xFFFFFFFFu, kk, off);
                if (ok < kk) kk = ok;
            }
            if (lane == 0) rowbest[wid] = kk;
        }
        __syncthreads();
        if (tid == 0) {
            for (int r = 0; r < nr; r++) {
                unsigned long long kk = rowbest[r];
                int   j    = (int)(kk & 0xFFFFFFFFull);
                float cmin = o2f((unsigned)(kk >> 32));
                int   i    = base + r;
                u[i] = (double)cmin;                    // fp32 value, exact in double
                if (p[j] == 0) p[j] = (short)i;
                else           plist[npend++] = (short)i;
            }
        }
        __syncthreads();
    }

    // ================= Phase B: JV phases for pending rows only =================
    const double DINF = 1e300;
    double v[CPT], d[CPT];
    #pragma unroll
    for (int t = 0; t < CPT; t++) v[t] = 0.0;

    const int np = npend;
    int par = 0;

    for (int pi = 0; pi < np; pi++) {
        const int i = plist[pi];
        unsigned usedmask = 0;
        #pragma unroll
        for (int t = 0; t < CPT; t++) d[t] = DINF;

        int    i0 = i, j0 = 0, jend = 0;
        double minVal = 0.0;

        while (true) {
            const double h1 = minVal - u[i0] + 1.0;   // folds the "1 - dot" constant
            const float  gx = gns[(i0 - 1) * 3 + 0];
            const float  gy = gns[(i0 - 1) * 3 + 1];
            const float  gz = gns[(i0 - 1) * 3 + 2];

            // relax free columns (exact f64); track local argmin (smallest j on ties)
            double best  = DINF;
            int    bestj = M + 1;
            #pragma unroll
            for (int t = 0; t < CPT; t++) {
                if (!((usedmask >> t) & 1u)) {
                    int   j   = tid + t * NT + 1;
                    float dot = fmaf(q2[t], gz, fmaf(q1[t], gy, q0[t] * gx));
                    double r  = (h1 - v[t]) - (double)dot;
                    if (r < d[t]) { d[t] = r; way[j] = (unsigned short)j0; }
                    if (d[t] < best) { best = d[t]; bestj = j; }
                }
            }
            // warp argmin on (value, index)
            #pragma unroll
            for (int off = 16; off; off >>= 1) {
                double ov = __shfl_down_sync(0xFFFFFFFFu, best,  off);
                int    oj = __shfl_down_sync(0xFFFFFFFFu, bestj, off);
                if (ov < best || (ov == best && oj < bestj)) { best = ov; bestj = oj; }
            }
            if (lane == 0) { wkey[par][wid] = ord64(best); wjj[par][wid] = bestj; }
            __syncthreads();   // the ONLY barrier in the step

            unsigned long long gk = wkey[par][lane & 15];
            int                gj = wjj[par][lane & 15];
            #pragma unroll
            for (int off = 8; off; off >>= 1) {
                unsigned long long ok = __shfl_xor_sync(0xFFFFFFFFu, gk, off);
                int                oj = __shfl_xor_sync(0xFFFFFFFFu, gj, off);
                if (ok < gk || (ok == gk && oj < gj)) { gk = ok; gj = oj; }
            }
            minVal = unord64(gk);
            const int j1 = gj;
            par ^= 1;

            const int pmatch = p[j1];        // p stable during the phase
            if (pmatch == 0) { jend = j1; break; }

            { int c = j1 - 1; if ((c & (NT - 1)) == tid) usedmask |= 1u << (c >> LOGNT); }
            i0 = pmatch;
            j0 = j1;
        }

        // phase-end dual updates (scanned set only), BEFORE augmentation
        #pragma unroll
        for (int t = 0; t < CPT; t++) {
            if ((usedmask >> t) & 1u) {
                double adj = minVal - d[t];
                v[t] -= adj;
                int j = tid + t * NT + 1;
                u[p[j]] += adj;              // distinct rows across scanned cols
            }
        }
        if (tid == 0) u[i] += minVal;
        __syncthreads();

        if (tid == 0) {                      // augment along predecessor chain
            int j = jend;
            while (true) {
                int jp = way[j];
                if (jp == 0) { p[j] = (short)i; break; }
                p[j] = p[jp];
                j = jp;
            }
        }
        __syncthreads();
    }

    // ---- write outputs: [0] per_prop_gt_inds, [1] proposal_matched_mask ----
    float* outInds = out + (size_t)b * M;
    float* outMask = out + (size_t)BATCH * M + (size_t)b * M;
    #pragma unroll
    for (int t = 0; t < CPT; t++) {
        int c = tid + t * NT;
        int r = p[c + 1];
        outInds[c] = (r > 0) ? (float)(r - 1) : 0.0f;
        outMask[c] = (r > 0) ? 1.0f : 0.0f;
    }
}

extern "C" void kernel_launch(void* const* d_in, const int* in_sizes, int n_in,
                              void* d_out, int out_size) {
    // metadata order: cls_prob[0], gt_box_present[1], num_actual_gt[2],
    //                 gt_normal_normalized[3], query_normals[4]
    const int*   nag = (const int*)  d_in[2];
    const float* gtn = (const float*)d_in[3];
    const float* qn  = (const float*)d_in[4];
    matcher_kernel<<<BATCH, NT>>>(nag, gtn, qn, (float*)d_out);
}

// round 13
// speedup vs baseline: 9.9717x; 1.8101x over previous
#include <cuda_runtime.h>
#include <cstdint>
#include <math_constants.h>

// Problem constants
#define BATCH 64
#define M     4096   // NPROP (columns)
#define NGTC  128    // max GT (rows)
#define NT    512    // threads per CTA (assign kernel)
#define CPT   (M/NT) // 8 columns per thread
#define NW    (NT/32)// 16 warps
#define LOGNT 9      // log2(NT)

// rowmin kernel config
#define K1NT   256
#define K1CPT  (M/K1NT)  // 16
#define K1NW   (K1NT/32) // 8
#define RT     8         // rows per tile
#define NTILES (NGTC/RT) // 16

#define KINF 0xFFFFFFFFFFFFFFFFull

// Order-preserving float <-> uint32
__device__ __forceinline__ unsigned f2o(float f) {
    unsigned x = __float_as_uint(f);
    return x ^ ((x & 0x80000000u) ? 0xFFFFFFFFu : 0x80000000u);
}
__device__ __forceinline__ float o2f(unsigned x) {
    unsigned w = (x & 0x80000000u) ? (x ^ 0x80000000u) : ~x;
    return __uint_as_float(w);
}
// Order-preserving double <-> uint64
__device__ __forceinline__ unsigned long long ord64(double x) {
    long long s = __double_as_longlong(x);
    return (unsigned long long)s ^ ((unsigned long long)(s >> 63) | 0x8000000000000000ull);
}
__device__ __forceinline__ double unord64(unsigned long long k) {
    long long b = (k & 0x8000000000000000ull) ? (long long)(k ^ 0x8000000000000000ull)
                                              : (long long)(~k);
    return __longlong_as_double(b);
}

// Scratch: per-(batch,row) packed (ord32 cost << 32) | argmin column (1-based)
__device__ unsigned long long g_rowkey[BATCH][NGTC];

// ============================================================================
// Kernel 1: chip-wide per-row argmin.  grid (BATCH, NTILES), block K1NT.
// ============================================================================
__global__ __launch_bounds__(K1NT)
void rowmin_kernel(const int*   __restrict__ nag,
                   const float* __restrict__ gtn,   // [B][NGT][3]
                   const float* __restrict__ qn)    // [M][3]
{
    const int b    = blockIdx.x;
    const int base = blockIdx.y * RT;               // 0-based first row of tile
    const int k    = nag[b];
    if (base >= k) return;
    const int nr   = min(RT, k - base);

    const int tid  = threadIdx.x;
    const int lane = tid & 31;
    const int wid  = tid >> 5;

    __shared__ unsigned long long awk[RT][K1NW];

    // query normals: 16 columns per thread, strided
    float q0[K1CPT], q1[K1CPT], q2[K1CPT];
    #pragma unroll
    for (int t = 0; t < K1CPT; t++) {
        int c = tid + t * K1NT;
        q0[t] = qn[c * 3 + 0];
        q1[t] = qn[c * 3 + 1];
        q2[t] = qn[c * 3 + 2];
    }

    for (int r = 0; r < nr; r++) {
        const float gx = gtn[((size_t)b * NGTC + base + r) * 3 + 0];
        const float gy = gtn[((size_t)b * NGTC + base + r) * 3 + 1];
        const float gz = gtn[((size_t)b * NGTC + base + r) * 3 + 2];
        float bcr = CUDART_INF_F; int bjr = M;
        #pragma unroll
        for (int t = 0; t < K1CPT; t++) {
            float dot = fmaf(q2[t], gz, fmaf(q1[t], gy, q0[t] * gx));
            float cf  = 1.0f - dot;                 // matches reference C bit-for-bit
            if (cf < bcr) { bcr = cf; bjr = tid + t * K1NT + 1; }  // first-min => smallest j
        }
        unsigned long long kk = ((unsigned long long)f2o(bcr) << 32) | (unsigned)bjr;
        #pragma unroll
        for (int off = 16; off; off >>= 1) {
            unsigned long long ok = __shfl_xor_sync(0xFFFFFFFFu, kk, off);
            if (ok < kk) kk = ok;                   // min cost, then min j
        }
        if (lane == 0) awk[r][wid] = kk;
    }
    __syncthreads();
    if (wid < nr) {                                 // warp w finishes row w
        unsigned long long kk = awk[wid][lane & 7];
        #pragma unroll
        for (int off = 4; off; off >>= 1) {
            unsigned long long ok = __shfl_xor_sync(0xFFFFFFFFu, kk, off);
            if (ok < kk) kk = ok;
        }
        if (lane == 0) g_rowkey[b][base + wid] = kk;
    }
}

// ============================================================================
// Kernel 2: greedy claim + JV phases for collisions + outputs. grid BATCH.
// ============================================================================
__global__ __launch_bounds__(NT, 1)
void assign_kernel(const int*   __restrict__ nag,
                   const float* __restrict__ gtn,
                   const float* __restrict__ qn,
                   float*       __restrict__ out)   // [2][B][M] : inds then mask
{
    const int b    = blockIdx.x;
    const int tid  = threadIdx.x;
    const int lane = tid & 31;
    const int wid  = tid >> 5;

    __shared__ short              p[M + 1];        // column -> row (1-based), 0 = free
    __shared__ unsigned short     way[M + 1];
    __shared__ int                claim[M + 1];    // greedy claim arbitration
    __shared__ double             u[NGTC + 1];
    __shared__ float              gns[NGTC * 3];
    __shared__ unsigned long long rk[NGTC];        // cached row keys
    __shared__ unsigned long long wkey[2][NW];
    __shared__ int                wjj[2][NW];
    __shared__ short              plist[NGTC];
    __shared__ int                npend;

    const int k = nag[b];

    for (int j = tid; j <= M; j += NT) { p[j] = 0; claim[j] = 0x7FFFFFFF; }
    for (int j = tid; j < k * 3; j += NT) gns[j] = gtn[(size_t)b * NGTC * 3 + j];
    for (int idx = tid; idx < k; idx += NT) rk[idx] = g_rowkey[b][idx];

    float q0[CPT], q1[CPT], q2[CPT];
    #pragma unroll
    for (int t = 0; t < CPT; t++) {
        int c = tid + t * NT;
        q0[t] = qn[c * 3 + 0];
        q1[t] = qn[c * 3 + 1];
        q2[t] = qn[c * 3 + 2];
    }
    __syncthreads();

    // ---- parallel greedy claim: winner of column = smallest row wanting it ----
    for (int idx = tid; idx < k; idx += NT) {
        int j = (int)(rk[idx] & 0xFFFFFFFFull);
        atomicMin(&claim[j], idx + 1);
    }
    __syncthreads();
    for (int idx = tid; idx < k; idx += NT) {
        int i = idx + 1;
        int j = (int)(rk[idx] & 0xFFFFFFFFull);
        u[i] = (double)o2f((unsigned)(rk[idx] >> 32));   // row dual = row min (fp32 exact)
        if (claim[j] == i) p[j] = (short)i;
    }
    __syncthreads();
    if (tid == 0) {                                  // pending rows, ascending i
        int np = 0;
        for (int idx = 0; idx < k; idx++) {
            int j = (int)(rk[idx] & 0xFFFFFFFFull);
            if (claim[j] != idx + 1) plist[np++] = (short)(idx + 1);
        }
        npend = np;
    }
    __syncthreads();

    // ---- JV phases for pending rows only ----
    const double DINF = 1e300;
    double v[CPT], d[CPT];
    #pragma unroll
    for (int t = 0; t < CPT; t++) v[t] = 0.0;

    const int np = npend;
    int par = 0;

    for (int pi = 0; pi < np; pi++) {
        const int i = plist[pi];
        unsigned usedmask = 0;
        #pragma unroll
        for (int t = 0; t < CPT; t++) d[t] = DINF;

        int    i0 = i, j0 = 0, jend = 0;
        double minVal = 0.0;

        while (true) {
            const double h1 = minVal - u[i0] + 1.0;   // folds the "1 - dot" constant
            const float  gx = gns[(i0 - 1) * 3 + 0];
            const float  gy = gns[(i0 - 1) * 3 + 1];
            const float  gz = gns[(i0 - 1) * 3 + 2];

            // relax free columns (exact f64); local argmin, smallest j on ties
            double best  = DINF;
            int    bestj = M + 1;
            #pragma unroll
            for (int t = 0; t < CPT; t++) {
                if (!((usedmask >> t) & 1u)) {
                    int   j   = tid + t * NT + 1;
                    float dot = fmaf(q2[t], gz, fmaf(q1[t], gy, q0[t] * gx));
                    double r  = (h1 - v[t]) - (double)dot;
                    if (r < d[t]) { d[t] = r; way[j] = (unsigned short)j0; }
                    if (d[t] < best) { best = d[t]; bestj = j; }
                }
            }
            #pragma unroll
            for (int off = 16; off; off >>= 1) {
                double ov = __shfl_down_sync(0xFFFFFFFFu, best,  off);
                int    oj = __shfl_down_sync(0xFFFFFFFFu, bestj, off);
                if (ov < best || (ov == best && oj < bestj)) { best = ov; bestj = oj; }
            }
            if (lane == 0) { wkey[par][wid] = ord64(best); wjj[par][wid] = bestj; }
            __syncthreads();   // the ONLY barrier in the step

            unsigned long long gk = wkey[par][lane & 15];
            int                gj = wjj[par][lane & 15];
            #pragma unroll
            for (int off = 8; off; off >>= 1) {
                unsigned long long ok = __shfl_xor_sync(0xFFFFFFFFu, gk, off);
                int                oj = __shfl_xor_sync(0xFFFFFFFFu, gj, off);
                if (ok < gk || (ok == gk && oj < gj)) { gk = ok; gj = oj; }
            }
            minVal = unord64(gk);
            const int j1 = gj;
            par ^= 1;

            const int pmatch = p[j1];
            if (pmatch == 0) { jend = j1; break; }

            { int c = j1 - 1; if ((c & (NT - 1)) == tid) usedmask |= 1u << (c >> LOGNT); }
            i0 = pmatch;
            j0 = j1;
        }

        // phase-end dual updates (scanned set only), BEFORE augmentation
        #pragma unroll
        for (int t = 0; t < CPT; t++) {
            if ((usedmask >> t) & 1u) {
                double adj = minVal - d[t];
                v[t] -= adj;
                int j = tid + t * NT + 1;
                u[p[j]] += adj;              // distinct rows across scanned cols
            }
        }
        if (tid == 0) u[i] += minVal;
        __syncthreads();

        if (tid == 0) {                      // augment along predecessor chain
            int j = jend;
            while (true) {
                int jp = way[j];
                if (jp == 0) { p[j] = (short)i; break; }
                p[j] = p[jp];
                j = jp;
            }
        }
        __syncthreads();
    }

    // ---- outputs: [0] per_prop_gt_inds, [1] proposal_matched_mask ----
    float* outInds = out + (size_t)b * M;
    float* outMask = out + (size_t)BATCH * M + (size_t)b * M;
    #pragma unroll
    for (int t = 0; t < CPT; t++) {
        int c = tid + t * NT;
        int r = p[c + 1];
        outInds[c] = (r > 0) ? (float)(r - 1) : 0.0f;
        outMask[c] = (r > 0) ? 1.0f : 0.0f;
    }
}

extern "C" void kernel_launch(void* const* d_in, const int* in_sizes, int n_in,
                              void* d_out, int out_size) {
    // metadata order: cls_prob[0], gt_box_present[1], num_actual_gt[2],
    //                 gt_normal_normalized[3], query_normals[4]
    const int*   nag = (const int*)  d_in[2];
    const float* gtn = (const float*)d_in[3];
    const float* qn  = (const float*)d_in[4];
    dim3 g1(BATCH, NTILES);
    rowmin_kernel<<<g1, K1NT>>>(nag, gtn, qn);
    assign_kernel<<<BATCH, NT>>>(nag, gtn, qn, (float*)d_out);
}

// round 14
// speedup vs baseline: 11.5184x; 1.1551x over previous
#include <cuda_runtime.h>
#include <cstdint>
#include <math_constants.h>

// Problem constants
#define BATCH 64
#define M     4096   // NPROP (columns)
#define NGTC  128    // max GT (rows)
#define NT    512    // threads per CTA (assign kernel)
#define CPT   (M/NT) // 8 columns per thread
#define NW    (NT/32)// 16 warps
#define LOGNT 9      // log2(NT)

// rowmin kernel config
#define K1NT   256
#define K1CPT  (M/K1NT)  // 16
#define K1NW   (K1NT/32) // 8
#define RT     8         // rows per tile
#define NTILES (NGTC/RT) // 16

#define FREEROW 0x7FFFFFFF

// Order-preserving float <-> uint32
__device__ __forceinline__ unsigned f2o(float f) {
    unsigned x = __float_as_uint(f);
    return x ^ ((x & 0x80000000u) ? 0xFFFFFFFFu : 0x80000000u);
}
__device__ __forceinline__ float o2f(unsigned x) {
    unsigned w = (x & 0x80000000u) ? (x ^ 0x80000000u) : ~x;
    return __uint_as_float(w);
}
// Order-preserving double <-> uint64
__device__ __forceinline__ unsigned long long ord64(double x) {
    long long s = __double_as_longlong(x);
    return (unsigned long long)s ^ ((unsigned long long)(s >> 63) | 0x8000000000000000ull);
}
__device__ __forceinline__ double unord64(unsigned long long k) {
    long long b = (k & 0x8000000000000000ull) ? (long long)(k ^ 0x8000000000000000ull)
                                              : (long long)(~k);
    return __longlong_as_double(b);
}

// Scratch: per-(batch,row) packed (ord32 cost << 32) | argmin column (1-based)
__device__ unsigned long long g_rowkey[BATCH][NGTC];

// ============================================================================
// Kernel 1: chip-wide per-row argmin.  grid (BATCH, NTILES), block K1NT.
// ============================================================================
__global__ __launch_bounds__(K1NT)
void rowmin_kernel(const int*   __restrict__ nag,
                   const float* __restrict__ gtn,   // [B][NGT][3]
                   const float* __restrict__ qn)    // [M][3]
{
    const int b    = blockIdx.x;
    const int base = blockIdx.y * RT;               // 0-based first row of tile
    const int k    = nag[b];
    if (base >= k) return;
    const int nr   = min(RT, k - base);

    const int tid  = threadIdx.x;
    const int lane = tid & 31;
    const int wid  = tid >> 5;

    __shared__ unsigned long long awk[RT][K1NW];

    // query normals: 16 columns per thread, strided
    float q0[K1CPT], q1[K1CPT], q2[K1CPT];
    #pragma unroll
    for (int t = 0; t < K1CPT; t++) {
        int c = tid + t * K1NT;
        q0[t] = qn[c * 3 + 0];
        q1[t] = qn[c * 3 + 1];
        q2[t] = qn[c * 3 + 2];
    }

    for (int r = 0; r < nr; r++) {
        const float gx = gtn[((size_t)b * NGTC + base + r) * 3 + 0];
        const float gy = gtn[((size_t)b * NGTC + base + r) * 3 + 1];
        const float gz = gtn[((size_t)b * NGTC + base + r) * 3 + 2];
        float bcr = CUDART_INF_F; int bjr = M;
        #pragma unroll
        for (int t = 0; t < K1CPT; t++) {
            float dot = fmaf(q2[t], gz, fmaf(q1[t], gy, q0[t] * gx));
            float cf  = 1.0f - dot;                 // matches reference C bit-for-bit
            if (cf < bcr) { bcr = cf; bjr = tid + t * K1NT + 1; }  // first-min => smallest j
        }
        unsigned long long kk = ((unsigned long long)f2o(bcr) << 32) | (unsigned)bjr;
        #pragma unroll
        for (int off = 16; off; off >>= 1) {
            unsigned long long ok = __shfl_xor_sync(0xFFFFFFFFu, kk, off);
            if (ok < kk) kk = ok;                   // min cost, then min j
        }
        if (lane == 0) awk[r][wid] = kk;
    }
    __syncthreads();
    if (wid < nr) {                                 // warp w finishes row w
        unsigned long long kk = awk[wid][lane & 7];
        #pragma unroll
        for (int off = 4; off; off >>= 1) {
            unsigned long long ok = __shfl_xor_sync(0xFFFFFFFFu, kk, off);
            if (ok < kk) kk = ok;
        }
        if (lane == 0) g_rowkey[b][base + wid] = kk;
    }
}

// ============================================================================
// Kernel 2: greedy claim + JV phases for collisions + outputs. grid BATCH.
// ============================================================================
__global__ __launch_bounds__(NT, 1)
void assign_kernel(const int*   __restrict__ nag,
                   const float* __restrict__ gtn,
                   const float* __restrict__ qn,
                   float*       __restrict__ out)   // [2][B][M] : inds then mask
{
    const int b    = blockIdx.x;
    const int tid  = threadIdx.x;
    const int lane = tid & 31;
    const int wid  = tid >> 5;

    __shared__ int                p[M + 1];        // column -> row (1-based), FREEROW = free
    __shared__ unsigned short     way[M + 1];
    __shared__ double             u[NGTC + 1];
    __shared__ float              gns[NGTC * 3];
    __shared__ unsigned long long rk[NGTC];        // cached row keys
    __shared__ unsigned long long wkey[2][NW];
    __shared__ int                wjj[2][NW];
    __shared__ short              plist[NGTC];
    __shared__ int                wcnt[4];         // pending counts per claim-warp
    __shared__ int                npend;

    const int k = nag[b];

    for (int j = tid; j <= M; j += NT) p[j] = FREEROW;
    for (int j = tid; j < k * 3; j += NT) gns[j] = gtn[(size_t)b * NGTC * 3 + j];
    for (int idx = tid; idx < k; idx += NT) rk[idx] = g_rowkey[b][idx];
    __syncthreads();

    // ---- parallel greedy claim: atomicMin writes winner row directly into p ----
    if (tid < k) {
        int j = (int)(rk[tid] & 0xFFFFFFFFull);
        u[tid + 1] = (double)o2f((unsigned)(rk[tid] >> 32));  // row dual = row min
        atomicMin(&p[j], tid + 1);
    }
    __syncthreads();

    // ---- parallel pending-list build (ascending row order) ----
    if (tid < NGTC) {   // 4 warps participate
        bool pend = false;
        if (tid < k) {
            int j = (int)(rk[tid] & 0xFFFFFFFFull);
            pend = (p[j] != tid + 1);                 // lost the claim
        }
        unsigned m  = __ballot_sync(0xFFFFFFFFu, pend);
        if (lane == 0) wcnt[wid] = __popc(m);
        __syncwarp();
        // store rank within warp; cross-warp offsets after barrier
        if (pend) {
            int rank = __popc(m & ((1u << lane) - 1u));
            // temporary park: position within warp segment recorded via rank; we
            // need wcnt of lower warps -> finish after __syncthreads below
            plist[wid * 32 + rank] = (short)(tid + 1);  // staged per-warp compact
        }
        if (lane == 0) wcnt[wid] |= (__popc(m) << 16); // (same value; keep simple)
    }
    __syncthreads();
    // compact staged per-warp segments into final ascending list
    if (tid == 0) {
        int np = 0;
        #pragma unroll
        for (int w = 0; w < 4; w++) {
            int c = wcnt[w] & 0xFFFF;
            for (int r = 0; r < c; r++) plist[np + r] = plist[w * 32 + r];
            np += c;
        }
        npend = np;
    }
    __syncthreads();

    const int np = npend;

    if (np > 0) {
        // ---- per-thread query normals (needed only for phases) ----
        float q0[CPT], q1[CPT], q2[CPT];
        #pragma unroll
        for (int t = 0; t < CPT; t++) {
            int c = tid + t * NT;
            q0[t] = qn[c * 3 + 0];
            q1[t] = qn[c * 3 + 1];
            q2[t] = qn[c * 3 + 2];
        }

        const double DINF = 1e300;
        double v[CPT], d[CPT];
        #pragma unroll
        for (int t = 0; t < CPT; t++) v[t] = 0.0;

        int par = 0;

        for (int pi = 0; pi < np; pi++) {
            const int i = plist[pi];
            unsigned usedmask = 0;
            #pragma unroll
            for (int t = 0; t < CPT; t++) d[t] = DINF;

            int    i0 = i, j0 = 0, jend = 0;
            double minVal = 0.0;

            while (true) {
                const double h1 = minVal - u[i0] + 1.0;  // folds the "1 - dot" constant
                const float  gx = gns[(i0 - 1) * 3 + 0];
                const float  gy = gns[(i0 - 1) * 3 + 1];
                const float  gz = gns[(i0 - 1) * 3 + 2];

                // relax free columns (exact f64); local argmin, smallest j on ties
                double best  = DINF;
                int    bestj = M + 1;
                #pragma unroll
                for (int t = 0; t < CPT; t++) {
                    if (!((usedmask >> t) & 1u)) {
                        int   j   = tid + t * NT + 1;
                        float dot = fmaf(q2[t], gz, fmaf(q1[t], gy, q0[t] * gx));
                        double r  = (h1 - v[t]) - (double)dot;
                        if (r < d[t]) { d[t] = r; way[j] = (unsigned short)j0; }
                        if (d[t] < best) { best = d[t]; bestj = j; }
                    }
                }
                #pragma unroll
                for (int off = 16; off; off >>= 1) {
                    double ov = __shfl_down_sync(0xFFFFFFFFu, best,  off);
                    int    oj = __shfl_down_sync(0xFFFFFFFFu, bestj, off);
                    if (ov < best || (ov == best && oj < bestj)) { best = ov; bestj = oj; }
                }
                if (lane == 0) { wkey[par][wid] = ord64(best); wjj[par][wid] = bestj; }
                __syncthreads();   // the ONLY barrier in the step

                unsigned long long gk = wkey[par][lane & 15];
                int                gj = wjj[par][lane & 15];
                #pragma unroll
                for (int off = 8; off; off >>= 1) {
                    unsigned long long ok = __shfl_xor_sync(0xFFFFFFFFu, gk, off);
                    int                oj = __shfl_xor_sync(0xFFFFFFFFu, gj, off);
                    if (ok < gk || (ok == gk && oj < gj)) { gk = ok; gj = oj; }
                }
                minVal = unord64(gk);
                const int j1 = gj;
                par ^= 1;

                const int pmatch = p[j1];
                if (pmatch == FREEROW) { jend = j1; break; }

                { int c = j1 - 1; if ((c & (NT - 1)) == tid) usedmask |= 1u << (c >> LOGNT); }
                i0 = pmatch;
                j0 = j1;
            }

            // phase-end dual updates (scanned set only), BEFORE augmentation
            #pragma unroll
            for (int t = 0; t < CPT; t++) {
                if ((usedmask >> t) & 1u) {
                    double adj = minVal - d[t];
                    v[t] -= adj;
                    int j = tid + t * NT + 1;
                    u[p[j]] += adj;              // distinct rows across scanned cols
                }
            }
            if (tid == 0) u[i] += minVal;
            __syncthreads();

            if (tid == 0) {                      // augment along predecessor chain
                int j = jend;
                while (true) {
                    int jp = way[j];
                    if (jp == 0) { p[j] = i; break; }
                    p[j] = p[jp];
                    j = jp;
                }
            }
            __syncthreads();
        }
    }

    // ---- outputs: [0] per_prop_gt_inds, [1] proposal_matched_mask ----
    float* outInds = out + (size_t)b * M;
    float* outMask = out + (size_t)BATCH * M + (size_t)b * M;
    #pragma unroll
    for (int t = 0; t < CPT; t++) {
        int c = tid + t * NT;
        int r = p[c + 1];
        bool matched = (r != FREEROW);
        outInds[c] = matched ? (float)(r - 1) : 0.0f;
        outMask[c] = matched ? 1.0f : 0.0f;
    }
}

extern "C" void kernel_launch(void* const* d_in, const int* in_sizes, int n_in,
                              void* d_out, int out_size) {
    // metadata order: cls_prob[0], gt_box_present[1], num_actual_gt[2],
    //                 gt_normal_normalized[3], query_normals[4]
    const int*   nag = (const int*)  d_in[2];
    const float* gtn = (const float*)d_in[3];
    const float* qn  = (const float*)d_in[4];
    dim3 g1(BATCH, NTILES);
    rowmin_kernel<<<g1, K1NT>>>(nag, gtn, qn);
    assign_kernel<<<BATCH, NT>>>(nag, gtn, qn, (float*)d_out);
}